// round 8
// baseline (speedup 1.0000x reference)
#include <cuda_runtime.h>
#include <math.h>
#include <stdint.h>
#include <stddef.h>

// Problem constants (VanillaRNN_30623116821140)
#define T_STEPS 2048
#define BATCH   64
#define NIN     128
#define NHID    512
#define NOUT    64

#define CPG 8   // CTAs per cluster (column slices)
#define BPC 4   // batch rows per cluster

// ---------------------------------------------------------------------------
// XLA EmitFastTanh (llvm_ir/math_ops.cc) — exact port. This is what BOTH the
// XLA GPU and CPU backends use for f32 tanh (NOT CUDA tanhf).
//   clamp to +-7.99881172180175781; r = x*P7(x^2)/Q4(x^2); |x|<4e-4 -> x
// Horner with FMA (Eigen pmadd / LLVM-contracted form).
// ---------------------------------------------------------------------------
__device__ __forceinline__ float xla_tanh(float x) {
    const float kClamp = 7.99881172180175781f;
    float ax = fabsf(x);
    float xc = fminf(fmaxf(x, -kClamp), kClamp);
    float x2 = __fmul_rn(xc, xc);
    float np;
    np = -2.76076847742355e-16f;
    np = fmaf(np, x2, 2.00018790482477e-13f);
    np = fmaf(np, x2, -8.60467152213735e-11f);
    np = fmaf(np, x2, 5.12229709037114e-08f);
    np = fmaf(np, x2, 1.48572235717979e-05f);
    np = fmaf(np, x2, 6.37261928875436e-04f);
    np = fmaf(np, x2, 4.89352455891786e-03f);
    float num = __fmul_rn(xc, np);
    float dp;
    dp = 1.19825839466702e-06f;
    dp = fmaf(dp, x2, 1.18534705686654e-04f);
    dp = fmaf(dp, x2, 2.26843463243900e-03f);
    dp = fmaf(dp, x2, 4.89352518554385e-03f);
    float r = __fdiv_rn(num, dp);
    return (ax < 0.0004f) ? x : r;
}

// ---------------------------------------------------------------------------
// PTX helpers (proven deterministic in R5/R7)
// ---------------------------------------------------------------------------
__device__ __forceinline__ uint32_t smem_u32(const void* p) {
    uint32_t a;
    asm("{ .reg .u64 t; cvta.to.shared.u64 t, %1; cvt.u32.u64 %0, t; }"
        : "=r"(a) : "l"(p));
    return a;
}
__device__ __forceinline__ uint32_t ctarank() {
    uint32_t r; asm("mov.u32 %0, %%cluster_ctarank;" : "=r"(r)); return r;
}
__device__ __forceinline__ void mbar_init(uint32_t addr, uint32_t count) {
    asm volatile("mbarrier.init.shared.b64 [%0], %1;" :: "r"(addr), "r"(count) : "memory");
}
__device__ __forceinline__ void mbar_arrive_peer(uint32_t addr, uint32_t peer) {
    asm volatile(
        "{ .reg .b32 r; mapa.shared::cluster.u32 r, %0, %1;\n\t"
        "mbarrier.arrive.release.cluster.shared::cluster.b64 _, [r]; }"
        :: "r"(addr), "r"(peer) : "memory");
}
__device__ __forceinline__ void mbar_wait(uint32_t addr, uint32_t parity) {
    uint32_t done;
    do {
        asm volatile(
            "{ .reg .pred p;\n\t"
            "mbarrier.try_wait.parity.acquire.cluster.shared::cta.b64 p, [%1], %2, 0x989680;\n\t"
            "selp.b32 %0, 1, 0, p; }"
            : "=r"(done) : "r"(addr), "r"(parity) : "memory");
    } while (!done);
}
__device__ __forceinline__ void cluster_sync_() {
    asm volatile("barrier.cluster.arrive.aligned;" ::: "memory");
    asm volatile("barrier.cluster.wait.aligned;" ::: "memory");
}

// ---------------------------------------------------------------------------
// Kernel 1: ux = u @ W_uh + b_hh.  One thread per output element.
// Single-accumulator ASCENDING-k fmaf chain (matches cuBLAS-SIMT / Eigen gebp
// per-element order), bias added AFTER the full dot (separate XLA add op).
// ---------------------------------------------------------------------------
__global__ __launch_bounds__(256) void k_ux(const float* __restrict__ u,
                                            const float* __restrict__ W_uh,
                                            const float* __restrict__ b_hh,
                                            float* __restrict__ hall) {
    const int idx = blockIdx.x * 256 + threadIdx.x;
    const int m = idx >> 9;          // row in (T*B)
    const int c = idx & 511;         // hid col
    const float* ur = u + (size_t)m * NIN;
    float acc = 0.f;
#pragma unroll 8
    for (int k = 0; k < NIN; ++k)
        acc = fmaf(ur[k], __ldg(W_uh + (size_t)k * NHID + c), acc);
    hall[(size_t)m * NHID + c] = __fadd_rn(acc, __ldg(b_hh + c));
}

// ---------------------------------------------------------------------------
// Kernel 2: persistent scan, cluster mbarrier sync (proven scaffold).
// 16 clusters x 8 CTAs x 256 threads = 32768 threads = one OUTPUT ELEMENT
// per thread. Each output: ONE ascending-k fmaf chain over all 512 k
// (NO split-k, NO reduction tree) -> same sum order as a single-accumulator
// SGEMM. Then pre = dot + ux (one add), h = xla_tanh(pre). In-place.
// W_hh slice (512x64 = 128 KB) is L1-resident after step 1.
// ---------------------------------------------------------------------------
__global__ __launch_bounds__(256) __cluster_dims__(CPG, 1, 1)
void k_scan(const float* __restrict__ W_hh, float* __restrict__ hall) {
    __shared__ float sH[BPC][512];
    __shared__ __align__(8) unsigned long long mbar_s;

    const int tid  = threadIdx.x;
    const uint32_t rank = ctarank();
    const int g    = blockIdx.x / CPG;
    const int cs   = (int)rank * 64;
    const int r0   = g * BPC;
    const uint32_t mb = smem_u32(&mbar_s);

    if (tid == 0) mbar_init(mb, CPG);
    cluster_sync_();

    const int r   = tid >> 6;            // 0..3   batch row within cluster
    const int c   = tid & 63;            // 0..63  col within slice
    const float* Wc = W_hh + cs + c;     // this thread's W column

    // t = 0 : h_0 = tanh(0 @ W + ux_0) = xla_tanh(ux_0)   (dot == exact 0)
    {
        size_t gi = (size_t)(r0 + r) * NHID + cs + c;
        hall[gi] = xla_tanh(hall[gi]);
    }
    __syncthreads();
    if (tid < CPG) mbar_arrive_peer(mb, tid);

    uint32_t parity = 0;
    for (int t = 1; t < T_STEPS; ++t) {
        mbar_wait(mb, parity);
        parity ^= 1u;

        // prefetch own ux_t element
        size_t giF = (size_t)t * BATCH * NHID + (size_t)(r0 + r) * NHID + cs + c;
        float uxv = hall[giF];

        // load h_{t-1} (4 rows x 512) into smem
        const float* hprev = hall + (size_t)(t - 1) * BATCH * NHID;
        for (int i = tid; i < BPC * 128; i += 256) {
            int rr = i >> 7, q = (i & 127) << 2;
            *(float4*)(&sH[rr][q]) =
                *(const float4*)(hprev + (size_t)(r0 + rr) * NHID + q);
        }
        __syncthreads();

        // ONE ascending-k chain, single accumulator (cuBLAS/Eigen order)
        float acc = 0.f;
#pragma unroll 8
        for (int k = 0; k < NHID; ++k)
            acc = fmaf(sH[r][k], Wc[(size_t)k * NHID], acc);

        hall[giF] = xla_tanh(__fadd_rn(acc, uxv));
        __syncthreads();

        if (tid < CPG) mbar_arrive_peer(mb, tid);
    }

    cluster_sync_();
}

// ---------------------------------------------------------------------------
// Kernel 3: logits = h_{T-1} @ W_hy + b_hy.
// Single ascending-k chain per output; bias added after the full dot.
// ---------------------------------------------------------------------------
__global__ __launch_bounds__(256) void k_logits(const float* __restrict__ hall,
                                                const float* __restrict__ W_hy,
                                                const float* __restrict__ b_hy,
                                                float* __restrict__ logits) {
    const int tid = threadIdx.x;
    const int b = blockIdx.x * 4 + (tid >> 6);
    const int o = tid & 63;
    const float* hr = hall + (size_t)(T_STEPS - 1) * BATCH * NHID + (size_t)b * NHID;
    float acc = 0.f;
#pragma unroll 4
    for (int h = 0; h < NHID; ++h)
        acc = fmaf(__ldg(hr + h), __ldg(W_hy + (size_t)h * NOUT + o), acc);
    logits[b * NOUT + o] = __fadd_rn(acc, __ldg(b_hy + o));
}

// ---------------------------------------------------------------------------
extern "C" void kernel_launch(void* const* d_in, const int* in_sizes, int n_in,
                              void* d_out, int out_size) {
    // Bind inputs by element count (pairwise-distinct).
    const float *u = 0, *W_uh = 0, *W_hh = 0, *W_hy = 0, *b_hh = 0, *b_hy = 0;
    for (int i = 0; i < n_in; ++i) {
        switch (in_sizes[i]) {
            case 16777216: u    = (const float*)d_in[i]; break; // 2048*64*128
            case 262144:   W_hh = (const float*)d_in[i]; break; // 512*512
            case 65536:    W_uh = (const float*)d_in[i]; break; // 128*512
            case 32768:    W_hy = (const float*)d_in[i]; break; // 512*64
            case 512:      b_hh = (const float*)d_in[i]; break;
            case 64:       b_hy = (const float*)d_in[i]; break;
            default: break;
        }
    }

    // Output layout A (confirmed by R6 norm algebra): [logits | h_all]
    float* out    = (float*)d_out;
    float* logits = out;
    float* hall   = out + (size_t)BATCH * NOUT;
    (void)out_size;

    k_ux<<<(T_STEPS * BATCH * NHID) / 256, 256>>>(u, W_uh, b_hh, hall);
    k_scan<<<16 * CPG, 256>>>(W_hh, hall);
    k_logits<<<BATCH / 4, 256>>>(hall, W_hy, b_hy, logits);
}

// round 9
// speedup vs baseline: 1.7991x; 1.7991x over previous
#include <cuda_runtime.h>
#include <math.h>
#include <stdint.h>
#include <stddef.h>

// Problem constants (VanillaRNN_30623116821140)
#define T_STEPS 2048
#define BATCH   64
#define NIN     128
#define NHID    512
#define NOUT    64

#define CPG 8   // CTAs per cluster (column slices of 64)
#define BPC 4   // batch rows per cluster

// Scan smem: W slice [512][64] + transposed h [512][4]
#define SCAN_SMEM_FLOATS (NHID * 64 + NHID * 4)
#define SCAN_SMEM_BYTES  (SCAN_SMEM_FLOATS * 4)   // 139,264 B

// ---------------------------------------------------------------------------
// XLA EmitFastTanh — exact port (bit-validated in R8: rel_err == 0.0)
// ---------------------------------------------------------------------------
__device__ __forceinline__ float xla_tanh(float x) {
    const float kClamp = 7.99881172180175781f;
    float ax = fabsf(x);
    float xc = fminf(fmaxf(x, -kClamp), kClamp);
    float x2 = __fmul_rn(xc, xc);
    float np;
    np = -2.76076847742355e-16f;
    np = fmaf(np, x2, 2.00018790482477e-13f);
    np = fmaf(np, x2, -8.60467152213735e-11f);
    np = fmaf(np, x2, 5.12229709037114e-08f);
    np = fmaf(np, x2, 1.48572235717979e-05f);
    np = fmaf(np, x2, 6.37261928875436e-04f);
    np = fmaf(np, x2, 4.89352455891786e-03f);
    float num = __fmul_rn(xc, np);
    float dp;
    dp = 1.19825839466702e-06f;
    dp = fmaf(dp, x2, 1.18534705686654e-04f);
    dp = fmaf(dp, x2, 2.26843463243900e-03f);
    dp = fmaf(dp, x2, 4.89352518554385e-03f);
    float r = __fdiv_rn(num, dp);
    return (ax < 0.0004f) ? x : r;
}

// ---------------------------------------------------------------------------
// PTX helpers (byte-identical sync pattern to R8 — proven)
// ---------------------------------------------------------------------------
__device__ __forceinline__ uint32_t smem_u32(const void* p) {
    uint32_t a;
    asm("{ .reg .u64 t; cvta.to.shared.u64 t, %1; cvt.u32.u64 %0, t; }"
        : "=r"(a) : "l"(p));
    return a;
}
__device__ __forceinline__ uint32_t ctarank() {
    uint32_t r; asm("mov.u32 %0, %%cluster_ctarank;" : "=r"(r)); return r;
}
__device__ __forceinline__ void mbar_init(uint32_t addr, uint32_t count) {
    asm volatile("mbarrier.init.shared.b64 [%0], %1;" :: "r"(addr), "r"(count) : "memory");
}
__device__ __forceinline__ void mbar_arrive_peer(uint32_t addr, uint32_t peer) {
    asm volatile(
        "{ .reg .b32 r; mapa.shared::cluster.u32 r, %0, %1;\n\t"
        "mbarrier.arrive.release.cluster.shared::cluster.b64 _, [r]; }"
        :: "r"(addr), "r"(peer) : "memory");
}
__device__ __forceinline__ void mbar_wait(uint32_t addr, uint32_t parity) {
    uint32_t done;
    do {
        asm volatile(
            "{ .reg .pred p;\n\t"
            "mbarrier.try_wait.parity.acquire.cluster.shared::cta.b64 p, [%1], %2, 0x989680;\n\t"
            "selp.b32 %0, 1, 0, p; }"
            : "=r"(done) : "r"(addr), "r"(parity) : "memory");
    } while (!done);
}
__device__ __forceinline__ void cluster_sync_() {
    asm volatile("barrier.cluster.arrive.aligned;" ::: "memory");
    asm volatile("barrier.cluster.wait.aligned;" ::: "memory");
}

// ---------------------------------------------------------------------------
// Kernel 1: ux = u @ W_uh + b_hh — TILED, bit-exact to the naive version:
// per output, ONE ascending-k single-accumulator fmaf chain, bias added after.
// grid (NHID/64, T*B/64) = (8, 2048), 256 threads.
// ---------------------------------------------------------------------------
__global__ __launch_bounds__(256) void k_ux(const float* __restrict__ u,
                                            const float* __restrict__ W_uh,
                                            const float* __restrict__ b_hh,
                                            float* __restrict__ hall) {
    __shared__ float sU[64][132];
    const int tid = threadIdx.x;
    const int m0  = blockIdx.y * 64;
    const int c0  = blockIdx.x * 64;

    for (int idx = tid; idx < 64 * 32; idx += 256) {
        int r = idx >> 5, q = (idx & 31) << 2;
        *(float4*)(&sU[r][q]) = *(const float4*)(u + (size_t)(m0 + r) * NIN + q);
    }
    __syncthreads();

    const int tr = tid >> 4;   // rows tr*4 .. tr*4+3
    const int tc = tid & 15;   // cols c0 + tc*4 .. +3

    float acc[4][4];
#pragma unroll
    for (int i = 0; i < 4; ++i)
#pragma unroll
        for (int j = 0; j < 4; ++j) acc[i][j] = 0.f;

#pragma unroll 4
    for (int k = 0; k < NIN; ++k) {      // ascending k, single acc per output
        float4 w = *(const float4*)(W_uh + (size_t)k * NHID + c0 + tc * 4);
#pragma unroll
        for (int i = 0; i < 4; ++i) {
            float a = sU[tr * 4 + i][k];
            acc[i][0] = fmaf(a, w.x, acc[i][0]);
            acc[i][1] = fmaf(a, w.y, acc[i][1]);
            acc[i][2] = fmaf(a, w.z, acc[i][2]);
            acc[i][3] = fmaf(a, w.w, acc[i][3]);
        }
    }

    float4 b = *(const float4*)(b_hh + c0 + tc * 4);
#pragma unroll
    for (int i = 0; i < 4; ++i) {
        float4 v = make_float4(__fadd_rn(acc[i][0], b.x), __fadd_rn(acc[i][1], b.y),
                               __fadd_rn(acc[i][2], b.z), __fadd_rn(acc[i][3], b.w));
        *(float4*)(hall + (size_t)(m0 + tr * 4 + i) * NHID + c0 + tc * 4) = v;
    }
}

// ---------------------------------------------------------------------------
// Kernel 2: persistent scan. Arithmetic bit-identical to R8 (one ascending
// 512-k fmaf chain per output, __fadd_rn(ux), xla_tanh); only operand
// RESIDENCY changed: W slice in SMEM (acquire-proof), h transposed in SMEM.
// 128 threads: thread (rp = tid>>6, c = tid&63) computes rows {2rp, 2rp+1}
// of column cs+c — 2 interleaved chains (ILP 2), 4 warps on 4 SMSPs.
// ---------------------------------------------------------------------------
__global__ __launch_bounds__(128) __cluster_dims__(CPG, 1, 1)
void k_scan(const float* __restrict__ W_hh, float* __restrict__ hall) {
    extern __shared__ float sm[];
    float* sW  = sm;                 // [512][64]   W_hh column slice
    float* sHT = sm + NHID * 64;     // [512][4]    h_{t-1} transposed
    __shared__ __align__(8) unsigned long long mbar_s;

    const int tid  = threadIdx.x;
    const uint32_t rank = ctarank();
    const int g    = blockIdx.x / CPG;
    const int cs   = (int)rank * 64;
    const int r0   = g * BPC;
    const uint32_t mb = smem_u32(&mbar_s);

    if (tid == 0) mbar_init(mb, CPG);

    // Load W slice into smem once: 512 x 64 fp32 = 128 KB
    for (int i = tid; i < NHID * 16; i += 128) {
        int row = i >> 4, q = (i & 15) << 2;
        *(float4*)(sW + row * 64 + q) =
            *(const float4*)(W_hh + (size_t)row * NHID + cs + q);
    }
    cluster_sync_();   // mbarriers initialized before any arrive

    const int rp = tid >> 6;             // 0..1 row-pair
    const int c  = tid & 63;             // 0..63 col in slice
    const int ra = r0 + 2 * rp;          // first row
    const int rb = ra + 1;               // second row

    // t = 0 : h_0 = xla_tanh(ux_0)
    {
        size_t gia = (size_t)ra * NHID + cs + c;
        size_t gib = (size_t)rb * NHID + cs + c;
        hall[gia] = xla_tanh(hall[gia]);
        hall[gib] = xla_tanh(hall[gib]);
    }
    __syncthreads();
    if (tid < CPG) mbar_arrive_peer(mb, tid);

    uint32_t parity = 0;
    for (int t = 1; t < T_STEPS; ++t) {
        mbar_wait(mb, parity);
        parity ^= 1u;

        // prefetch own ux_t elements
        size_t base = (size_t)t * BATCH * NHID;
        size_t giA = base + (size_t)ra * NHID + cs + c;
        size_t giB = base + (size_t)rb * NHID + cs + c;
        float uxA = hall[giA];
        float uxB = hall[giB];

        // load + transpose h_{t-1}: sHT[k][r] = h[r0+r][k]
        const float* hprev = hall + (size_t)(t - 1) * BATCH * NHID;
        for (int k = tid; k < NHID; k += 128) {
#pragma unroll
            for (int r = 0; r < BPC; ++r)
                sHT[k * 4 + r] = hprev[(size_t)(r0 + r) * NHID + k];
        }
        __syncthreads();

        // two ascending-k chains (rows ra, rb) — bit-identical order to R8
        const float* hp = sHT + 2 * rp;   // &sHT[k][2rp], stride 4 floats
        float a0 = 0.f, a1 = 0.f;
#pragma unroll 8
        for (int k = 0; k < NHID; ++k) {
            float  w  = sW[k * 64 + c];
            float2 h2 = *(const float2*)(hp + k * 4);
            a0 = fmaf(h2.x, w, a0);
            a1 = fmaf(h2.y, w, a1);
        }

        hall[giA] = xla_tanh(__fadd_rn(a0, uxA));
        hall[giB] = xla_tanh(__fadd_rn(a1, uxB));
        __syncthreads();   // protect sHT before next step's overwrite

        if (tid < CPG) mbar_arrive_peer(mb, tid);
    }

    cluster_sync_();
}

// ---------------------------------------------------------------------------
// Kernel 3: logits = h_{T-1} @ W_hy + b_hy (proven bit-exact)
// ---------------------------------------------------------------------------
__global__ __launch_bounds__(256) void k_logits(const float* __restrict__ hall,
                                                const float* __restrict__ W_hy,
                                                const float* __restrict__ b_hy,
                                                float* __restrict__ logits) {
    const int tid = threadIdx.x;
    const int b = blockIdx.x * 4 + (tid >> 6);
    const int o = tid & 63;
    const float* hr = hall + (size_t)(T_STEPS - 1) * BATCH * NHID + (size_t)b * NHID;
    float acc = 0.f;
#pragma unroll 4
    for (int h = 0; h < NHID; ++h)
        acc = fmaf(__ldg(hr + h), __ldg(W_hy + (size_t)h * NOUT + o), acc);
    logits[b * NOUT + o] = __fadd_rn(acc, __ldg(b_hy + o));
}

// ---------------------------------------------------------------------------
extern "C" void kernel_launch(void* const* d_in, const int* in_sizes, int n_in,
                              void* d_out, int out_size) {
    const float *u = 0, *W_uh = 0, *W_hh = 0, *W_hy = 0, *b_hh = 0, *b_hy = 0;
    for (int i = 0; i < n_in; ++i) {
        switch (in_sizes[i]) {
            case 16777216: u    = (const float*)d_in[i]; break; // 2048*64*128
            case 262144:   W_hh = (const float*)d_in[i]; break; // 512*512
            case 65536:    W_uh = (const float*)d_in[i]; break; // 128*512
            case 32768:    W_hy = (const float*)d_in[i]; break; // 512*64
            case 512:      b_hh = (const float*)d_in[i]; break;
            case 64:       b_hy = (const float*)d_in[i]; break;
            default: break;
        }
    }

    // Output layout A (proven): [logits | h_all]
    float* out    = (float*)d_out;
    float* logits = out;
    float* hall   = out + (size_t)BATCH * NOUT;
    (void)out_size;

    cudaFuncSetAttribute(k_scan, cudaFuncAttributeMaxDynamicSharedMemorySize,
                         SCAN_SMEM_BYTES);

    k_ux<<<dim3(NHID / 64, (T_STEPS * BATCH) / 64), 256>>>(u, W_uh, b_hh, hall);
    k_scan<<<16 * CPG, 128, SCAN_SMEM_BYTES>>>(W_hh, hall);
    k_logits<<<BATCH / 4, 256>>>(hall, W_hy, b_hy, logits);
}

// round 10
// speedup vs baseline: 2.3038x; 1.2805x over previous
#include <cuda_runtime.h>
#include <math.h>
#include <stdint.h>
#include <stddef.h>

// Problem constants (VanillaRNN_30623116821140)
#define T_STEPS 2048
#define BATCH   64
#define NIN     128
#define NHID    512
#define NOUT    64

#define CPG 8   // CTAs per cluster (column slices of 64)
#define BPC 4   // batch rows per cluster
#define STEP_BH (BATCH * NHID)   // 32768 floats per timestep

// Scan dynamic smem: W slice [512][64] + double-buffered transposed h [2][512][4]
#define SHT_BUF_FLOATS (NHID * BPC)                   // 2048
#define SCAN_SMEM_FLOATS (NHID * 64 + 2 * SHT_BUF_FLOATS)
#define SCAN_SMEM_BYTES  (SCAN_SMEM_FLOATS * 4)       // 147,456 B

// ---------------------------------------------------------------------------
// XLA EmitFastTanh — exact port (bit-validated: rel_err == 0.0 in R8/R9)
// ---------------------------------------------------------------------------
__device__ __forceinline__ float xla_tanh(float x) {
    const float kClamp = 7.99881172180175781f;
    float ax = fabsf(x);
    float xc = fminf(fmaxf(x, -kClamp), kClamp);
    float x2 = __fmul_rn(xc, xc);
    float np;
    np = -2.76076847742355e-16f;
    np = fmaf(np, x2, 2.00018790482477e-13f);
    np = fmaf(np, x2, -8.60467152213735e-11f);
    np = fmaf(np, x2, 5.12229709037114e-08f);
    np = fmaf(np, x2, 1.48572235717979e-05f);
    np = fmaf(np, x2, 6.37261928875436e-04f);
    np = fmaf(np, x2, 4.89352455891786e-03f);
    float num = __fmul_rn(xc, np);
    float dp;
    dp = 1.19825839466702e-06f;
    dp = fmaf(dp, x2, 1.18534705686654e-04f);
    dp = fmaf(dp, x2, 2.26843463243900e-03f);
    dp = fmaf(dp, x2, 4.89352518554385e-03f);
    float r = __fdiv_rn(num, dp);
    return (ax < 0.0004f) ? x : r;
}

// ---------------------------------------------------------------------------
// PTX helpers
// ---------------------------------------------------------------------------
__device__ __forceinline__ uint32_t smem_u32(const void* p) {
    uint32_t a;
    asm("{ .reg .u64 t; cvta.to.shared.u64 t, %1; cvt.u32.u64 %0, t; }"
        : "=r"(a) : "l"(p));
    return a;
}
__device__ __forceinline__ uint32_t ctarank() {
    uint32_t r; asm("mov.u32 %0, %%cluster_ctarank;" : "=r"(r)); return r;
}
__device__ __forceinline__ void mbar_init(uint32_t addr, uint32_t count) {
    asm volatile("mbarrier.init.shared.b64 [%0], %1;" :: "r"(addr), "r"(count) : "memory");
}
__device__ __forceinline__ void mbar_arrive_peer(uint32_t addr, uint32_t peer) {
    asm volatile(
        "{ .reg .b32 r; mapa.shared::cluster.u32 r, %0, %1;\n\t"
        "mbarrier.arrive.release.cluster.shared::cluster.b64 _, [r]; }"
        :: "r"(addr), "r"(peer) : "memory");
}
__device__ __forceinline__ void mbar_wait(uint32_t addr, uint32_t parity) {
    uint32_t done;
    do {
        asm volatile(
            "{ .reg .pred p;\n\t"
            "mbarrier.try_wait.parity.acquire.cluster.shared::cta.b64 p, [%1], %2, 0x989680;\n\t"
            "selp.b32 %0, 1, 0, p; }"
            : "=r"(done) : "r"(addr), "r"(parity) : "memory");
    } while (!done);
}
__device__ __forceinline__ void cluster_sync_() {
    asm volatile("barrier.cluster.arrive.aligned;" ::: "memory");
    asm volatile("barrier.cluster.wait.aligned;" ::: "memory");
}
__device__ __forceinline__ uint32_t mapa_peer(uint32_t local_addr, uint32_t peer) {
    uint32_t r;
    asm("mapa.shared::cluster.u32 %0, %1, %2;" : "=r"(r) : "r"(local_addr), "r"(peer));
    return r;
}
__device__ __forceinline__ void dsmem_st64(uint32_t raddr, float a, float b) {
    unsigned long long v;
    asm("mov.b64 %0, {%1, %2};" : "=l"(v) : "f"(a), "f"(b));
    asm volatile("st.shared::cluster.b64 [%0], %1;" :: "r"(raddr), "l"(v) : "memory");
}

// ---------------------------------------------------------------------------
// Kernel 1: ux = u @ W_uh + b_hh (bit-exact single ascending chains; proven)
// ---------------------------------------------------------------------------
__global__ __launch_bounds__(256) void k_ux(const float* __restrict__ u,
                                            const float* __restrict__ W_uh,
                                            const float* __restrict__ b_hh,
                                            float* __restrict__ hall) {
    __shared__ float sU[64][132];
    const int tid = threadIdx.x;
    const int m0  = blockIdx.y * 64;
    const int c0  = blockIdx.x * 64;

    for (int idx = tid; idx < 64 * 32; idx += 256) {
        int r = idx >> 5, q = (idx & 31) << 2;
        *(float4*)(&sU[r][q]) = *(const float4*)(u + (size_t)(m0 + r) * NIN + q);
    }
    __syncthreads();

    const int tr = tid >> 4;
    const int tc = tid & 15;

    float acc[4][4];
#pragma unroll
    for (int i = 0; i < 4; ++i)
#pragma unroll
        for (int j = 0; j < 4; ++j) acc[i][j] = 0.f;

#pragma unroll 4
    for (int k = 0; k < NIN; ++k) {
        float4 w = *(const float4*)(W_uh + (size_t)k * NHID + c0 + tc * 4);
#pragma unroll
        for (int i = 0; i < 4; ++i) {
            float a = sU[tr * 4 + i][k];
            acc[i][0] = fmaf(a, w.x, acc[i][0]);
            acc[i][1] = fmaf(a, w.y, acc[i][1]);
            acc[i][2] = fmaf(a, w.z, acc[i][2]);
            acc[i][3] = fmaf(a, w.w, acc[i][3]);
        }
    }

    float4 b = *(const float4*)(b_hh + c0 + tc * 4);
#pragma unroll
    for (int i = 0; i < 4; ++i) {
        float4 v = make_float4(__fadd_rn(acc[i][0], b.x), __fadd_rn(acc[i][1], b.y),
                               __fadd_rn(acc[i][2], b.z), __fadd_rn(acc[i][3], b.w));
        *(float4*)(hall + (size_t)(m0 + tr * 4 + i) * NHID + c0 + tc * 4) = v;
    }
}

// ---------------------------------------------------------------------------
// Kernel 2: persistent scan. Arithmetic bit-identical to R9; h now exchanged
// via DSMEM (double-buffered transposed sHT), ux prefetched a step ahead,
// h_all global store moved off the critical path (after the release-arrive).
// 16 clusters x 8 CTAs, 128 threads; thread (rp,c) owns rows {2rp,2rp+1} of
// col cs+c (two ascending 512-k fmaf chains, ILP 2 — FFMA floor 2048 cyc).
// ---------------------------------------------------------------------------
__global__ __launch_bounds__(128) __cluster_dims__(CPG, 1, 1)
void k_scan(const float* __restrict__ W_hh, float* __restrict__ hall) {
    extern __shared__ float sm[];
    float* sW  = sm;                 // [512][64]   W_hh column slice
    float* sHT = sm + NHID * 64;     // [2][512][4] h transposed, double-buffered
    __shared__ __align__(8) unsigned long long mbar_s;

    const int tid  = threadIdx.x;
    const uint32_t rank = ctarank();
    const int g    = blockIdx.x / CPG;
    const int cs   = (int)rank * 64;
    const int r0   = g * BPC;
    const uint32_t mb = smem_u32(&mbar_s);

    if (tid == 0) mbar_init(mb, CPG);

    // Load W slice into smem once (512 x 64 fp32 = 128 KB)
    for (int i = tid; i < NHID * 16; i += 128) {
        int row = i >> 4, q = (i & 15) << 2;
        *(float4*)(sW + row * 64 + q) =
            *(const float4*)(W_hh + (size_t)row * NHID + cs + q);
    }

    const int rp = tid >> 6;             // 0..1 row pair
    const int c  = tid & 63;             // 0..63 col in slice
    const int ra = r0 + 2 * rp;
    const int rb = ra + 1;
    const size_t offA = (size_t)ra * NHID + cs + c;   // hall offset, row ra
    const size_t offB = (size_t)rb * NHID + cs + c;

    // Precompute remote DSMEM addresses of this thread's slot in buf 0 of all
    // 8 cluster CTAs: sHT[0][cs+c][2rp]  (buf1 = +8192 bytes, same peer).
    uint32_t dst0 = smem_u32(sHT) + (uint32_t)(((cs + c) * 4 + 2 * rp) * 4);
    uint32_t rdst[CPG];
#pragma unroll
    for (int j = 0; j < CPG; ++j) rdst[j] = mapa_peer(dst0, (uint32_t)j);

    cluster_sync_();   // mbarriers visible cluster-wide; W loaded (CTA-wide)

    // ---- t = 0 : h_0 = xla_tanh(ux_0) ----
    float hA = xla_tanh(hall[offA]);
    float hB = xla_tanh(hall[offB]);
#pragma unroll
    for (int j = 0; j < CPG; ++j) dsmem_st64(rdst[j], hA, hB);   // buf 0
    __syncthreads();
    if (tid < CPG) mbar_arrive_peer(mb, tid);
    hall[offA] = hA;                       // output store off critical path
    hall[offB] = hB;

    // Prefetch ux_1
    float uxA = hall[(size_t)STEP_BH + offA];
    float uxB = hall[(size_t)STEP_BH + offB];

    uint32_t parity = 0;
    for (int t = 1; t < T_STEPS; ++t) {
        mbar_wait(mb, parity);
        parity ^= 1u;

        // Prefetch ux_{t+1} (fully hidden under compute)
        float nA = 0.f, nB = 0.f;
        if (t + 1 < T_STEPS) {
            nA = hall[(size_t)(t + 1) * STEP_BH + offA];
            nB = hall[(size_t)(t + 1) * STEP_BH + offB];
        }

        // Two ascending-k chains — bit-identical order; h from local smem
        const float* hp = sHT + ((t - 1) & 1) * SHT_BUF_FLOATS + 2 * rp;
        float a0 = 0.f, a1 = 0.f;
#pragma unroll 8
        for (int k = 0; k < NHID; ++k) {
            float  w  = sW[k * 64 + c];
            float2 h2 = *(const float2*)(hp + k * 4);
            a0 = fmaf(h2.x, w, a0);
            a1 = fmaf(h2.y, w, a1);
        }

        hA = xla_tanh(__fadd_rn(a0, uxA));
        hB = xla_tanh(__fadd_rn(a1, uxB));

        // Broadcast h_t into buf (t&1) of all 8 cluster CTAs (incl. self)
        uint32_t boff = (uint32_t)((t & 1) * (SHT_BUF_FLOATS * 4));
#pragma unroll
        for (int j = 0; j < CPG; ++j) dsmem_st64(rdst[j] + boff, hA, hB);
        __syncthreads();
        if (tid < CPG) mbar_arrive_peer(mb, tid);

        // Off critical path: h_all output + register rotate
        hall[(size_t)t * STEP_BH + offA] = hA;
        hall[(size_t)t * STEP_BH + offB] = hB;
        uxA = nA; uxB = nB;
    }

    cluster_sync_();   // peers may still be storing into our smem
}

// ---------------------------------------------------------------------------
// Kernel 3: logits = h_{T-1} @ W_hy + b_hy (proven bit-exact)
// ---------------------------------------------------------------------------
__global__ __launch_bounds__(256) void k_logits(const float* __restrict__ hall,
                                                const float* __restrict__ W_hy,
                                                const float* __restrict__ b_hy,
                                                float* __restrict__ logits) {
    const int tid = threadIdx.x;
    const int b = blockIdx.x * 4 + (tid >> 6);
    const int o = tid & 63;
    const float* hr = hall + (size_t)(T_STEPS - 1) * STEP_BH + (size_t)b * NHID;
    float acc = 0.f;
#pragma unroll 4
    for (int h = 0; h < NHID; ++h)
        acc = fmaf(__ldg(hr + h), __ldg(W_hy + (size_t)h * NOUT + o), acc);
    logits[b * NOUT + o] = __fadd_rn(acc, __ldg(b_hy + o));
}

// ---------------------------------------------------------------------------
extern "C" void kernel_launch(void* const* d_in, const int* in_sizes, int n_in,
                              void* d_out, int out_size) {
    const float *u = 0, *W_uh = 0, *W_hh = 0, *W_hy = 0, *b_hh = 0, *b_hy = 0;
    for (int i = 0; i < n_in; ++i) {
        switch (in_sizes[i]) {
            case 16777216: u    = (const float*)d_in[i]; break; // 2048*64*128
            case 262144:   W_hh = (const float*)d_in[i]; break; // 512*512
            case 65536:    W_uh = (const float*)d_in[i]; break; // 128*512
            case 32768:    W_hy = (const float*)d_in[i]; break; // 512*64
            case 512:      b_hh = (const float*)d_in[i]; break;
            case 64:       b_hy = (const float*)d_in[i]; break;
            default: break;
        }
    }

    // Output layout A (proven): [logits | h_all]
    float* out    = (float*)d_out;
    float* logits = out;
    float* hall   = out + (size_t)BATCH * NOUT;
    (void)out_size;

    cudaFuncSetAttribute(k_scan, cudaFuncAttributeMaxDynamicSharedMemorySize,
                         SCAN_SMEM_BYTES);

    k_ux<<<dim3(NHID / 64, (T_STEPS * BATCH) / 64), 256>>>(u, W_uh, b_hh, hall);
    k_scan<<<16 * CPG, 128, SCAN_SMEM_BYTES>>>(W_hh, hall);
    k_logits<<<BATCH / 4, 256>>>(hall, W_hy, b_hy, logits);
}

// round 14
// speedup vs baseline: 3.6896x; 1.6015x over previous
#include <cuda_runtime.h>
#include <math.h>
#include <stdint.h>
#include <stddef.h>

// Problem constants (VanillaRNN_30623116821140)
#define T_STEPS 2048
#define BATCH   64
#define NIN     128
#define NHID    512
#define NOUT    64

#define CPG 8   // CTAs per cluster (column slices of 64)
#define BPC 4   // batch rows per cluster
#define STEP_BH (BATCH * NHID)   // 32768 floats per timestep

// Scan dynamic smem:
//   sW  [512][64]            W_hh column slice            (32768 floats)
//   sHT [2][2][512][2]       h double-buffer, [buf][rp][k][row-in-pair]
//                            (2 * 2048 floats)
//   + 128 floats padding (pipeline over-read safety)
#define SHT_BUF_FLOATS (NHID * BPC)                   // 2048
#define SCAN_SMEM_FLOATS (NHID * 64 + 2 * SHT_BUF_FLOATS + 128)
#define SCAN_SMEM_BYTES  (SCAN_SMEM_FLOATS * 4)       // 147,968 B

// ---------------------------------------------------------------------------
// XLA EmitFastTanh — exact port (bit-validated: rel_err == 0.0 since R8)
// ---------------------------------------------------------------------------
__device__ __forceinline__ float xla_tanh(float x) {
    const float kClamp = 7.99881172180175781f;
    float ax = fabsf(x);
    float xc = fminf(fmaxf(x, -kClamp), kClamp);
    float x2 = __fmul_rn(xc, xc);
    float np;
    np = -2.76076847742355e-16f;
    np = fmaf(np, x2, 2.00018790482477e-13f);
    np = fmaf(np, x2, -8.60467152213735e-11f);
    np = fmaf(np, x2, 5.12229709037114e-08f);
    np = fmaf(np, x2, 1.48572235717979e-05f);
    np = fmaf(np, x2, 6.37261928875436e-04f);
    np = fmaf(np, x2, 4.89352455891786e-03f);
    float num = __fmul_rn(xc, np);
    float dp;
    dp = 1.19825839466702e-06f;
    dp = fmaf(dp, x2, 1.18534705686654e-04f);
    dp = fmaf(dp, x2, 2.26843463243900e-03f);
    dp = fmaf(dp, x2, 4.89352518554385e-03f);
    float r = __fdiv_rn(num, dp);
    return (ax < 0.0004f) ? x : r;
}

// ---------------------------------------------------------------------------
// PTX helpers
// ---------------------------------------------------------------------------
__device__ __forceinline__ uint32_t smem_u32(const void* p) {
    uint32_t a;
    asm("{ .reg .u64 t; cvta.to.shared.u64 t, %1; cvt.u32.u64 %0, t; }"
        : "=r"(a) : "l"(p));
    return a;
}
__device__ __forceinline__ uint32_t ctarank() {
    uint32_t r; asm("mov.u32 %0, %%cluster_ctarank;" : "=r"(r)); return r;
}
__device__ __forceinline__ void mbar_init(uint32_t addr, uint32_t count) {
    asm volatile("mbarrier.init.shared.b64 [%0], %1;" :: "r"(addr), "r"(count) : "memory");
}
__device__ __forceinline__ void mbar_arrive_peer(uint32_t addr, uint32_t peer) {
    asm volatile(
        "{ .reg .b32 r; mapa.shared::cluster.u32 r, %0, %1;\n\t"
        "mbarrier.arrive.release.cluster.shared::cluster.b64 _, [r]; }"
        :: "r"(addr), "r"(peer) : "memory");
}
__device__ __forceinline__ void mbar_wait(uint32_t addr, uint32_t parity) {
    uint32_t done;
    do {
        asm volatile(
            "{ .reg .pred p;\n\t"
            "mbarrier.try_wait.parity.acquire.cluster.shared::cta.b64 p, [%1], %2, 0x989680;\n\t"
            "selp.b32 %0, 1, 0, p; }"
            : "=r"(done) : "r"(addr), "r"(parity) : "memory");
    } while (!done);
}
__device__ __forceinline__ void cluster_sync_() {
    asm volatile("barrier.cluster.arrive.aligned;" ::: "memory");
    asm volatile("barrier.cluster.wait.aligned;" ::: "memory");
}
__device__ __forceinline__ uint32_t mapa_peer(uint32_t local_addr, uint32_t peer) {
    uint32_t r;
    asm("mapa.shared::cluster.u32 %0, %1, %2;" : "=r"(r) : "r"(local_addr), "r"(peer));
    return r;
}
__device__ __forceinline__ void dsmem_st64(uint32_t raddr, float a, float b) {
    unsigned long long v;
    asm("mov.b64 %0, {%1, %2};" : "=l"(v) : "f"(a), "f"(b));
    asm volatile("st.shared::cluster.b64 [%0], %1;" :: "r"(raddr), "l"(v) : "memory");
}

// ---------------------------------------------------------------------------
// Kernel 1: ux = u @ W_uh + b_hh (bit-exact; unchanged since R9)
// ---------------------------------------------------------------------------
__global__ __launch_bounds__(256) void k_ux(const float* __restrict__ u,
                                            const float* __restrict__ W_uh,
                                            const float* __restrict__ b_hh,
                                            float* __restrict__ hall) {
    __shared__ float sU[64][132];
    const int tid = threadIdx.x;
    const int m0  = blockIdx.y * 64;
    const int c0  = blockIdx.x * 64;

    for (int idx = tid; idx < 64 * 32; idx += 256) {
        int r = idx >> 5, q = (idx & 31) << 2;
        *(float4*)(&sU[r][q]) = *(const float4*)(u + (size_t)(m0 + r) * NIN + q);
    }
    __syncthreads();

    const int tr = tid >> 4;
    const int tc = tid & 15;

    float acc[4][4];
#pragma unroll
    for (int i = 0; i < 4; ++i)
#pragma unroll
        for (int j = 0; j < 4; ++j) acc[i][j] = 0.f;

#pragma unroll 4
    for (int k = 0; k < NIN; ++k) {
        float4 w = *(const float4*)(W_uh + (size_t)k * NHID + c0 + tc * 4);
#pragma unroll
        for (int i = 0; i < 4; ++i) {
            float a = sU[tr * 4 + i][k];
            acc[i][0] = fmaf(a, w.x, acc[i][0]);
            acc[i][1] = fmaf(a, w.y, acc[i][1]);
            acc[i][2] = fmaf(a, w.z, acc[i][2]);
            acc[i][3] = fmaf(a, w.w, acc[i][3]);
        }
    }

    float4 b = *(const float4*)(b_hh + c0 + tc * 4);
#pragma unroll
    for (int i = 0; i < 4; ++i) {
        float4 v = make_float4(__fadd_rn(acc[i][0], b.x), __fadd_rn(acc[i][1], b.y),
                               __fadd_rn(acc[i][2], b.z), __fadd_rn(acc[i][3], b.w));
        *(float4*)(hall + (size_t)(m0 + tr * 4 + i) * NHID + c0 + tc * 4) = v;
    }
}

// ---------------------------------------------------------------------------
// Kernel 2: persistent scan — DSMEM exchange + manually software-pipelined
// inner loop. Arithmetic bit-identical: each output is ONE ascending-k fmaf
// chain over k=0..511 (only LOADS are restructured/reordered).
// Thread (rp = tid>>6, c = tid&63) owns rows {2rp, 2rp+1} of column cs+c.
// h layout: sHT[buf][rp][k][2] -> consumer reads float4 = 2 k's of its pair.
// ---------------------------------------------------------------------------
__global__ __launch_bounds__(128) __cluster_dims__(CPG, 1, 1)
void k_scan(const float* __restrict__ W_hh, float* __restrict__ hall) {
    extern __shared__ float sm[];
    float* sW  = sm;                 // [512][64]
    float* sHT = sm + NHID * 64;     // [2][2][512][2]
    __shared__ __align__(8) unsigned long long mbar_s;

    const int tid  = threadIdx.x;
    const uint32_t rank = ctarank();
    const int cs   = (int)rank * 64;
    const int r0   = (blockIdx.x / CPG) * BPC;
    const uint32_t mb = smem_u32(&mbar_s);

    if (tid == 0) mbar_init(mb, CPG);

    // Load W slice into smem once (512 x 64 fp32 = 128 KB)
    for (int i = tid; i < NHID * 16; i += 128) {
        int row = i >> 4, q = (i & 15) << 2;
        *(float4*)(sW + row * 64 + q) =
            *(const float4*)(W_hh + (size_t)row * NHID + cs + q);
    }

    const int rp = tid >> 6;             // 0..1 row pair
    const int c  = tid & 63;             // 0..63 col in slice
    const int ra = r0 + 2 * rp;
    const int rb = ra + 1;
    const size_t offA = (size_t)ra * NHID + cs + c;
    const size_t offB = (size_t)rb * NHID + cs + c;

    // Remote DSMEM addresses of this thread's h slot in buf 0 of all 8 CTAs:
    // sHT[0][rp][cs+c][0..1]  (8 B). buf1 = +8192 B on the same peer.
    uint32_t dst0 = smem_u32(sHT) +
                    (uint32_t)((rp * NHID * 2 + (cs + c) * 2) * 4);
    uint32_t rdst[CPG];
#pragma unroll
    for (int j = 0; j < CPG; ++j) rdst[j] = mapa_peer(dst0, (uint32_t)j);

    cluster_sync_();   // mbarriers visible; W loaded

    // ---- t = 0 : h_0 = xla_tanh(ux_0) ----
    float hA = xla_tanh(hall[offA]);
    float hB = xla_tanh(hall[offB]);
#pragma unroll
    for (int j = 0; j < CPG; ++j) dsmem_st64(rdst[j], hA, hB);   // buf 0
    __syncthreads();
    if (tid < CPG) mbar_arrive_peer(mb, tid);
    hall[offA] = hA;
    hall[offB] = hB;

    // Prefetch ux_1
    float uxA = hall[(size_t)STEP_BH + offA];
    float uxB = hall[(size_t)STEP_BH + offB];

    const float* sWc = sW + c;           // &sW[k=0][c], stride 64 floats

    uint32_t parity = 0;
    for (int t = 1; t < T_STEPS; ++t) {
        mbar_wait(mb, parity);
        parity ^= 1u;

        // Prefetch ux_{t+1} (hidden under compute)
        float nA = 0.f, nB = 0.f;
        if (t + 1 < T_STEPS) {
            nA = hall[(size_t)(t + 1) * STEP_BH + offA];
            nB = hall[(size_t)(t + 1) * STEP_BH + offB];
        }

        // h for my row pair, this step's buffer: [k][2], float4 = 2 k's
        const float* hp = sHT + ((t - 1) & 1) * SHT_BUF_FLOATS + rp * NHID * 2;

        // -------- software-pipelined ascending-k chain (blocks of 8 k) ----
        // Register stages A/B; prefetch next block while FMA-ing current.
        // Over-reads one block past k=511 into padded smem (never used).
        float  wA[8], wB[8];
        float4 hA4[4], hB4[4];          // 4 float4 = 8 k of the row pair

#pragma unroll
        for (int j = 0; j < 8; ++j) wA[j] = sWc[j * 64];
#pragma unroll
        for (int j = 0; j < 4; ++j) hA4[j] = *(const float4*)(hp + j * 4);

        float a0 = 0.f, a1 = 0.f;

#pragma unroll 1
        for (int blk = 0; blk < 64; blk += 2) {
            const int k1 = (blk + 1) * 8;
#pragma unroll
            for (int j = 0; j < 8; ++j) wB[j] = sWc[(k1 + j) * 64];
#pragma unroll
            for (int j = 0; j < 4; ++j)
                hB4[j] = *(const float4*)(hp + (k1 + j * 2) * 2);
#pragma unroll
            for (int j = 0; j < 4; ++j) {
                a0 = fmaf(hA4[j].x, wA[2 * j],     a0);
                a1 = fmaf(hA4[j].y, wA[2 * j],     a1);
                a0 = fmaf(hA4[j].z, wA[2 * j + 1], a0);
                a1 = fmaf(hA4[j].w, wA[2 * j + 1], a1);
            }
            const int k2 = (blk + 2) * 8;   // last iter: padded over-read
#pragma unroll
            for (int j = 0; j < 8; ++j) wA[j] = sWc[(k2 + j) * 64];
#pragma unroll
            for (int j = 0; j < 4; ++j)
                hA4[j] = *(const float4*)(hp + (k2 + j * 2) * 2);
#pragma unroll
            for (int j = 0; j < 4; ++j) {
                a0 = fmaf(hB4[j].x, wB[2 * j],     a0);
                a1 = fmaf(hB4[j].y, wB[2 * j],     a1);
                a0 = fmaf(hB4[j].z, wB[2 * j + 1], a0);
                a1 = fmaf(hB4[j].w, wB[2 * j + 1], a1);
            }
        }

        hA = xla_tanh(__fadd_rn(a0, uxA));
        hB = xla_tanh(__fadd_rn(a1, uxB));

        // Broadcast h_t into buf (t&1) of all 8 cluster CTAs
        uint32_t boff = (uint32_t)((t & 1) * (SHT_BUF_FLOATS * 4));
#pragma unroll
        for (int j = 0; j < CPG; ++j) dsmem_st64(rdst[j] + boff, hA, hB);
        __syncthreads();
        if (tid < CPG) mbar_arrive_peer(mb, tid);

        // Off critical path: h_all output + ux rotate
        hall[(size_t)t * STEP_BH + offA] = hA;
        hall[(size_t)t * STEP_BH + offB] = hB;
        uxA = nA; uxB = nB;
    }

    cluster_sync_();
}

// ---------------------------------------------------------------------------
// Kernel 3: logits = h_{T-1} @ W_hy + b_hy (proven bit-exact)
// ---------------------------------------------------------------------------
__global__ __launch_bounds__(256) void k_logits(const float* __restrict__ hall,
                                                const float* __restrict__ W_hy,
                                                const float* __restrict__ b_hy,
                                                float* __restrict__ logits) {
    const int tid = threadIdx.x;
    const int b = blockIdx.x * 4 + (tid >> 6);
    const int o = tid & 63;
    const float* hr = hall + (size_t)(T_STEPS - 1) * STEP_BH + (size_t)b * NHID;
    float acc = 0.f;
#pragma unroll 4
    for (int h = 0; h < NHID; ++h)
        acc = fmaf(__ldg(hr + h), __ldg(W_hy + (size_t)h * NOUT + o), acc);
    logits[b * NOUT + o] = __fadd_rn(acc, __ldg(b_hy + o));
}

// ---------------------------------------------------------------------------
extern "C" void kernel_launch(void* const* d_in, const int* in_sizes, int n_in,
                              void* d_out, int out_size) {
    const float *u = 0, *W_uh = 0, *W_hh = 0, *W_hy = 0, *b_hh = 0, *b_hy = 0;
    for (int i = 0; i < n_in; ++i) {
        switch (in_sizes[i]) {
            case 16777216: u    = (const float*)d_in[i]; break; // 2048*64*128
            case 262144:   W_hh = (const float*)d_in[i]; break; // 512*512
            case 65536:    W_uh = (const float*)d_in[i]; break; // 128*512
            case 32768:    W_hy = (const float*)d_in[i]; break; // 512*64
            case 512:      b_hh = (const float*)d_in[i]; break;
            case 64:       b_hy = (const float*)d_in[i]; break;
            default: break;
        }
    }

    // Output layout A (proven): [logits | h_all]
    float* out    = (float*)d_out;
    float* logits = out;
    float* hall   = out + (size_t)BATCH * NOUT;
    (void)out_size;

    cudaFuncSetAttribute(k_scan, cudaFuncAttributeMaxDynamicSharedMemorySize,
                         SCAN_SMEM_BYTES);

    k_ux<<<dim3(NHID / 64, (T_STEPS * BATCH) / 64), 256>>>(u, W_uh, b_hh, hall);
    k_scan<<<16 * CPG, 128, SCAN_SMEM_BYTES>>>(W_hh, hall);
    k_logits<<<BATCH / 4, 256>>>(hall, W_hy, b_hy, logits);
}